// round 1
// baseline (speedup 1.0000x reference)
#include <cuda_runtime.h>
#include <math.h>

#define NN    50000
#define EE    800000
#define EMBED 64
#define NH    8
#define HD    8
#define MAXD  100
#define SCALE 0.35355339059327373f   // HD^-0.5 = 8^-0.5

// Scratch (no allocation allowed -> __device__ globals)
__device__ float g_q[NN * EMBED];
__device__ float g_k[NN * EMBED];
__device__ float g_v[NN * EMBED];
__device__ float g_acc[NN * EMBED];   // unnormalized output accumulator
__device__ float g_den[NN * NH];      // softmax denominators

// ---------------------------------------------------------------------------
// Zero the accumulators (needed every launch; graph replays reuse buffers)
// ---------------------------------------------------------------------------
__global__ void zero_kernel() {
    int i = blockIdx.x * blockDim.x + threadIdx.x;
    const int n_acc4 = NN * EMBED / 4;
    const int n_den4 = NN * NH / 4;
    if (i < n_acc4) {
        ((float4*)g_acc)[i] = make_float4(0.f, 0.f, 0.f, 0.f);
    } else {
        int j = i - n_acc4;
        if (j < n_den4) ((float4*)g_den)[j] = make_float4(0.f, 0.f, 0.f, 0.f);
    }
}

// ---------------------------------------------------------------------------
// Fused QKV projection: q/k/v = x @ W{q,k,v} + b{q,k,v}
// One thread per node; weights staged in shared memory; float4 smem reads.
// ---------------------------------------------------------------------------
__global__ __launch_bounds__(256) void qkv_kernel(
    const float* __restrict__ x,
    const float* __restrict__ Wq, const float* __restrict__ bq,
    const float* __restrict__ Wk, const float* __restrict__ bk,
    const float* __restrict__ Wv, const float* __restrict__ bv)
{
    __shared__ float sW[3][64][64];   // 48 KB
    __shared__ float sb[3][64];
    int tid = threadIdx.x;
    float* sWf = &sW[0][0][0];
    for (int i = tid; i < 4096; i += 256) {
        sWf[i]          = Wq[i];
        sWf[4096 + i]   = Wk[i];
        sWf[8192 + i]   = Wv[i];
    }
    if (tid < 64) { sb[0][tid] = bq[tid]; sb[1][tid] = bk[tid]; sb[2][tid] = bv[tid]; }
    __syncthreads();

    int n = blockIdx.x * 256 + tid;
    if (n >= NN) return;

    float xr[64];
    const float4* xp = (const float4*)(x + (size_t)n * 64);
    #pragma unroll
    for (int i = 0; i < 16; i++) {
        float4 t = xp[i];
        xr[4*i+0] = t.x; xr[4*i+1] = t.y; xr[4*i+2] = t.z; xr[4*i+3] = t.w;
    }

    float* outs[3] = { g_q, g_k, g_v };
    #pragma unroll 1
    for (int m = 0; m < 3; m++) {
        float4* op = (float4*)(outs[m] + (size_t)n * 64);
        #pragma unroll 1
        for (int c4 = 0; c4 < 16; c4++) {
            float4 acc = ((const float4*)sb[m])[c4];
            #pragma unroll
            for (int k = 0; k < 64; k++) {
                float4 w = *(const float4*)&sW[m][k][c4 * 4];
                acc.x += xr[k] * w.x;
                acc.y += xr[k] * w.y;
                acc.z += xr[k] * w.z;
                acc.w += xr[k] * w.w;
            }
            op[c4] = acc;
        }
    }
}

// ---------------------------------------------------------------------------
// Edge kernel: 8 threads per edge (one per head).
//   score = (q[row]·(k[col]+rel_k[bin])) * SCALE    (per head)
//   ex    = exp(score)            (segment-max skipped: scores are O(1))
//   den[row,h]      += ex
//   acc[row,h,:]    += ex * (v[col,h,:] + rel_v[bin,h,:])
// Grid is an exact multiple of 8 threads/edge (EE*8 % 256 == 0), so every
// lane in every warp is active for the shuffle.
// ---------------------------------------------------------------------------
__global__ __launch_bounds__(256) void edge_kernel(
    const int*   __restrict__ ei,     // [2, EE]
    const float* __restrict__ pos,    // [NN, 3]
    const float* __restrict__ relk,   // [201, 8, 8]
    const float* __restrict__ relv)   // [201, 8, 8]
{
    int t = blockIdx.x * 256 + threadIdx.x;
    int e = t >> 3;
    if (e >= EE) return;
    int h    = t & 7;
    int lane = threadIdx.x & 31;

    int row = ei[e];
    int col = ei[EE + e];

    // distance bin (computed once per edge, broadcast to the 8 head-lanes)
    float dist = 0.f;
    if (h == 0) {
        float dx = pos[row*3+0] - pos[col*3+0];
        float dy = pos[row*3+1] - pos[col*3+1];
        float dz = pos[row*3+2] - pos[col*3+2];
        dist = sqrtf(dx*dx + dy*dy + dz*dz);
    }
    dist = __shfl_sync(0xFFFFFFFFu, dist, lane & 24);
    int bin = (int)(dist * 10.0f);      // trunc toward zero, dist >= 0
    if (bin > MAXD) bin = MAXD;
    bin += MAXD;

    const float4* qp  = (const float4*)(g_q  + (size_t)row * 64 + h * 8);
    const float4* kp  = (const float4*)(g_k  + (size_t)col * 64 + h * 8);
    const float4* vp  = (const float4*)(g_v  + (size_t)col * 64 + h * 8);
    const float4* rkp = (const float4*)(relk + (size_t)bin * 64 + h * 8);
    const float4* rvp = (const float4*)(relv + (size_t)bin * 64 + h * 8);

    float4 q0 = qp[0],  q1 = qp[1];
    float4 k0 = kp[0],  k1 = kp[1];
    float4 rk0 = rkp[0], rk1 = rkp[1];

    // q·k + q·rpk == q·(k+rpk)
    float s =
        q0.x*(k0.x+rk0.x) + q0.y*(k0.y+rk0.y) + q0.z*(k0.z+rk0.z) + q0.w*(k0.w+rk0.w) +
        q1.x*(k1.x+rk1.x) + q1.y*(k1.y+rk1.y) + q1.z*(k1.z+rk1.z) + q1.w*(k1.w+rk1.w);
    float ex = __expf(s * SCALE);

    atomicAdd(&g_den[(size_t)row * NH + h], ex);

    float4 v0 = vp[0],  v1 = vp[1];
    float4 rv0 = rvp[0], rv1 = rvp[1];

    float* op = g_acc + (size_t)row * 64 + h * 8;
    asm volatile("red.global.add.v4.f32 [%0], {%1,%2,%3,%4};" ::
                 "l"(op),
                 "f"(ex*(v0.x+rv0.x)), "f"(ex*(v0.y+rv0.y)),
                 "f"(ex*(v0.z+rv0.z)), "f"(ex*(v0.w+rv0.w)) : "memory");
    asm volatile("red.global.add.v4.f32 [%0], {%1,%2,%3,%4};" ::
                 "l"(op + 4),
                 "f"(ex*(v1.x+rv1.x)), "f"(ex*(v1.y+rv1.y)),
                 "f"(ex*(v1.z+rv1.z)), "f"(ex*(v1.w+rv1.w)) : "memory");
}

// ---------------------------------------------------------------------------
// Normalize by denominators, then out = t @ Wo + bo
// ---------------------------------------------------------------------------
__global__ __launch_bounds__(256) void out_kernel(
    const float* __restrict__ Wo, const float* __restrict__ bo,
    float* __restrict__ out)
{
    __shared__ float sW[64][64];      // 16 KB
    __shared__ float sb[64];
    int tid = threadIdx.x;
    for (int i = tid; i < 4096; i += 256) ((float*)sW)[i] = Wo[i];
    if (tid < 64) sb[tid] = bo[tid];
    __syncthreads();

    int n = blockIdx.x * 256 + tid;
    if (n >= NN) return;

    float xr[64];
    const float4* ap = (const float4*)(g_acc + (size_t)n * 64);
    #pragma unroll
    for (int hh = 0; hh < 8; hh++) {
        float den = g_den[(size_t)n * NH + hh];
        float inv = (den > 0.f) ? (1.0f / den) : 0.0f;  // empty segments -> 0
        float4 a0 = ap[hh*2+0];
        float4 a1 = ap[hh*2+1];
        xr[hh*8+0] = a0.x*inv; xr[hh*8+1] = a0.y*inv;
        xr[hh*8+2] = a0.z*inv; xr[hh*8+3] = a0.w*inv;
        xr[hh*8+4] = a1.x*inv; xr[hh*8+5] = a1.y*inv;
        xr[hh*8+6] = a1.z*inv; xr[hh*8+7] = a1.w*inv;
    }

    float4* op = (float4*)(out + (size_t)n * 64);
    #pragma unroll 1
    for (int c4 = 0; c4 < 16; c4++) {
        float4 acc = ((const float4*)sb)[c4];
        #pragma unroll
        for (int k = 0; k < 64; k++) {
            float4 w = *(const float4*)&sW[k][c4 * 4];
            acc.x += xr[k] * w.x;
            acc.y += xr[k] * w.y;
            acc.z += xr[k] * w.z;
            acc.w += xr[k] * w.w;
        }
        op[c4] = acc;
    }
}

// ---------------------------------------------------------------------------
extern "C" void kernel_launch(void* const* d_in, const int* in_sizes, int n_in,
                              void* d_out, int out_size)
{
    const float* x   = (const float*)d_in[0];
    const int*   ei  = (const int*)  d_in[1];
    const float* pos = (const float*)d_in[2];
    const float* Wq  = (const float*)d_in[3];
    const float* bq  = (const float*)d_in[4];
    const float* Wk  = (const float*)d_in[5];
    const float* bk  = (const float*)d_in[6];
    const float* Wv  = (const float*)d_in[7];
    const float* bv  = (const float*)d_in[8];
    const float* rk  = (const float*)d_in[9];
    const float* rv  = (const float*)d_in[10];
    const float* Wo  = (const float*)d_in[11];
    const float* bo  = (const float*)d_in[12];
    float* out = (float*)d_out;

    const int zero_threads = NN * (EMBED + NH) / 4;           // 900K
    zero_kernel<<<(zero_threads + 255) / 256, 256>>>();
    qkv_kernel <<<(NN + 255) / 256, 256>>>(x, Wq, bq, Wk, bk, Wv, bv);
    edge_kernel<<<(EE * 8) / 256, 256>>>(ei, pos, rk, rv);    // exact multiple
    out_kernel <<<(NN + 255) / 256, 256>>>(Wo, bo, out);
}

// round 2
// speedup vs baseline: 1.2055x; 1.2055x over previous
#include <cuda_runtime.h>
#include <math.h>

#define NN    50000
#define EE    800000
#define EMBED 64
#define NH    8
#define HD    8
#define MAXD  100
#define SCALE 0.35355339059327373f   // 8^-0.5

// Scratch (no allocation allowed -> __device__ globals)
__device__ float g_q[NN * EMBED];
__device__ float g_k[NN * EMBED];
__device__ float g_v[NN * EMBED];
__device__ float g_acc[NN * EMBED];
__device__ float g_den[NN * NH];

// ---------------------------------------------------------------------------
__global__ void zero_kernel() {
    int i = blockIdx.x * blockDim.x + threadIdx.x;
    const int n_acc4 = NN * EMBED / 4;
    const int n_den4 = NN * NH / 4;
    if (i < n_acc4) {
        ((float4*)g_acc)[i] = make_float4(0.f, 0.f, 0.f, 0.f);
    } else {
        int j = i - n_acc4;
        if (j < n_den4) ((float4*)g_den)[j] = make_float4(0.f, 0.f, 0.f, 0.f);
    }
}

// ---------------------------------------------------------------------------
// tf32 helpers
// ---------------------------------------------------------------------------
__device__ __forceinline__ unsigned f2tf32(float v) {
    unsigned r;
    asm("cvt.rna.tf32.f32 %0, %1;" : "=r"(r) : "f"(v));
    return r;
}

#define MMA_TF32(c0,c1,c2,c3,a0,a1,a2,a3,b0,b1)                               \
    asm volatile("mma.sync.aligned.m16n8k8.row.col.f32.tf32.tf32.f32 "        \
                 "{%0,%1,%2,%3},{%4,%5,%6,%7},{%8,%9},{%0,%1,%2,%3};"         \
                 : "+f"(c0), "+f"(c1), "+f"(c2), "+f"(c3)                     \
                 : "r"(a0), "r"(a1), "r"(a2), "r"(a3), "r"(b0), "r"(b1))

// ---------------------------------------------------------------------------
// QKV projection via tensor cores.
// Block = 256 threads (8 warps), 128 nodes per block, warp handles 16 nodes.
// Shared memory layout (dynamic):
//   sB   [24 nblk][8 kstep][32 lane][4] : fragment-ordered W (hi0,hi1,lo0,lo1)
//   sU   union: raw W [64][192]  -> later X tile [128][68] (padded)
//   sBias[192]
// ---------------------------------------------------------------------------
#define QKV_SB_F   (24 * 8 * 32 * 4)        // 24576 floats
#define QKV_SU_F   (64 * 192)               // 12288 floats (>= 128*68=8704)
#define QKV_SMEM_B ((QKV_SB_F + QKV_SU_F + 192) * 4)

__global__ __launch_bounds__(256) void qkv_mma(
    const float* __restrict__ x,
    const float* __restrict__ Wq, const float* __restrict__ bq,
    const float* __restrict__ Wk, const float* __restrict__ bk,
    const float* __restrict__ Wv, const float* __restrict__ bv)
{
    extern __shared__ float sm[];
    float* sB    = sm;
    float* sU    = sm + QKV_SB_F;
    float* sBias = sU + QKV_SU_F;
    const int tid = threadIdx.x;

    // phase 1: stage W coalesced into raw [k][192]
    for (int i = tid; i < 4096; i += 256) {
        int k = i >> 6, n = i & 63;
        sU[k * 192 + n]       = Wq[i];
        sU[k * 192 + n + 64]  = Wk[i];
        sU[k * 192 + n + 128] = Wv[i];
    }
    if (tid < 192)
        sBias[tid] = (tid < 64) ? bq[tid] : (tid < 128) ? bk[tid - 64] : bv[tid - 128];
    __syncthreads();

    // phase 2: fragment-order + tf32 hi/lo split
    for (int e = tid; e < 6144; e += 256) {
        int lane = e & 31, kstep = (e >> 5) & 7, nblk = e >> 8;
        int k0 = kstep * 8 + (lane & 3);
        int n  = nblk * 8 + (lane >> 2);
        float w0 = sU[k0 * 192 + n];
        float w1 = sU[(k0 + 4) * 192 + n];
        unsigned h0 = f2tf32(w0), h1 = f2tf32(w1);
        unsigned l0 = f2tf32(w0 - __uint_as_float(h0));
        unsigned l1 = f2tf32(w1 - __uint_as_float(h1));
        float4 fr = make_float4(__uint_as_float(h0), __uint_as_float(h1),
                                __uint_as_float(l0), __uint_as_float(l1));
        *(float4*)&sB[e * 4] = fr;
    }
    __syncthreads();

    // phase 3: stage X tile [128][68] (pad 68 avoids LDS bank conflicts)
    const int base = blockIdx.x * 128;
    for (int i = tid; i < 2048; i += 256) {        // float4 granularity
        int r = i >> 4, c4 = i & 15;
        int node = base + r;
        float4 t = (node < NN) ? ((const float4*)(x + (size_t)node * 64))[c4]
                               : make_float4(0.f, 0.f, 0.f, 0.f);
        *(float4*)&sU[r * 68 + c4 * 4] = t;
    }
    __syncthreads();

    // phase 4: mma
    const int w = tid >> 5, lane = tid & 31;
    const int grp = lane >> 2, tg = lane & 3;
    const float* xr0 = sU + (w * 16 + grp) * 68;
    const float* xr8 = sU + (w * 16 + grp + 8) * 68;

    unsigned ah[8][4], al[8][4];
    #pragma unroll
    for (int ks = 0; ks < 8; ks++) {
        float v0 = xr0[ks * 8 + tg],     v1 = xr8[ks * 8 + tg];
        float v2 = xr0[ks * 8 + tg + 4], v3 = xr8[ks * 8 + tg + 4];
        ah[ks][0] = f2tf32(v0); al[ks][0] = f2tf32(v0 - __uint_as_float(ah[ks][0]));
        ah[ks][1] = f2tf32(v1); al[ks][1] = f2tf32(v1 - __uint_as_float(ah[ks][1]));
        ah[ks][2] = f2tf32(v2); al[ks][2] = f2tf32(v2 - __uint_as_float(ah[ks][2]));
        ah[ks][3] = f2tf32(v3); al[ks][3] = f2tf32(v3 - __uint_as_float(ah[ks][3]));
    }

    const int row0 = base + w * 16 + grp;

    #pragma unroll 1
    for (int nb2 = 0; nb2 < 12; nb2++) {
        float cA0 = 0.f, cA1 = 0.f, cA2 = 0.f, cA3 = 0.f;
        float cB0 = 0.f, cB1 = 0.f, cB2 = 0.f, cB3 = 0.f;
        const float* pA = sB + ((nb2 * 2 + 0) * 256 + lane) * 4;
        const float* pB = sB + ((nb2 * 2 + 1) * 256 + lane) * 4;
        #pragma unroll
        for (int ks = 0; ks < 8; ks++) {
            float4 fA = *(const float4*)(pA + ks * 128);
            float4 fB = *(const float4*)(pB + ks * 128);
            unsigned bAh0 = __float_as_uint(fA.x), bAh1 = __float_as_uint(fA.y);
            unsigned bAl0 = __float_as_uint(fA.z), bAl1 = __float_as_uint(fA.w);
            unsigned bBh0 = __float_as_uint(fB.x), bBh1 = __float_as_uint(fB.y);
            unsigned bBl0 = __float_as_uint(fB.z), bBl1 = __float_as_uint(fB.w);
            MMA_TF32(cA0,cA1,cA2,cA3, ah[ks][0],ah[ks][1],ah[ks][2],ah[ks][3], bAh0,bAh1);
            MMA_TF32(cB0,cB1,cB2,cB3, ah[ks][0],ah[ks][1],ah[ks][2],ah[ks][3], bBh0,bBh1);
            MMA_TF32(cA0,cA1,cA2,cA3, al[ks][0],al[ks][1],al[ks][2],al[ks][3], bAh0,bAh1);
            MMA_TF32(cB0,cB1,cB2,cB3, al[ks][0],al[ks][1],al[ks][2],al[ks][3], bBh0,bBh1);
            MMA_TF32(cA0,cA1,cA2,cA3, ah[ks][0],ah[ks][1],ah[ks][2],ah[ks][3], bAl0,bAl1);
            MMA_TF32(cB0,cB1,cB2,cB3, ah[ks][0],ah[ks][1],ah[ks][2],ah[ks][3], bBl0,bBl1);
        }
        #pragma unroll
        for (int t = 0; t < 2; t++) {
            int nblk = nb2 * 2 + t;
            int m    = nblk >> 3;
            int ncol = (nblk & 7) * 8 + tg * 2;
            float b0 = sBias[nblk * 8 + tg * 2];
            float b1 = sBias[nblk * 8 + tg * 2 + 1];
            float c0 = (t ? cB0 : cA0) + b0, c1 = (t ? cB1 : cA1) + b1;
            float c2 = (t ? cB2 : cA2) + b0, c3 = (t ? cB3 : cA3) + b1;
            float* dst = (m == 0) ? g_q : (m == 1) ? g_k : g_v;
            if (row0 < NN)
                *(float2*)&dst[(size_t)row0 * 64 + ncol] = make_float2(c0, c1);
            if (row0 + 8 < NN)
                *(float2*)&dst[(size_t)(row0 + 8) * 64 + ncol] = make_float2(c2, c3);
        }
    }
}

// ---------------------------------------------------------------------------
// Edge kernel: unchanged from R1 (8 threads/edge, vector reduction atomics).
// ---------------------------------------------------------------------------
__global__ __launch_bounds__(256) void edge_kernel(
    const int*   __restrict__ ei,
    const float* __restrict__ pos,
    const float* __restrict__ relk,
    const float* __restrict__ relv)
{
    int t = blockIdx.x * 256 + threadIdx.x;
    int e = t >> 3;
    if (e >= EE) return;
    int h    = t & 7;
    int lane = threadIdx.x & 31;

    int row = ei[e];
    int col = ei[EE + e];

    float dist = 0.f;
    if (h == 0) {
        float dx = pos[row*3+0] - pos[col*3+0];
        float dy = pos[row*3+1] - pos[col*3+1];
        float dz = pos[row*3+2] - pos[col*3+2];
        dist = sqrtf(dx*dx + dy*dy + dz*dz);
    }
    dist = __shfl_sync(0xFFFFFFFFu, dist, lane & 24);
    int bin = (int)(dist * 10.0f);
    if (bin > MAXD) bin = MAXD;
    bin += MAXD;

    const float4* qp  = (const float4*)(g_q  + (size_t)row * 64 + h * 8);
    const float4* kp  = (const float4*)(g_k  + (size_t)col * 64 + h * 8);
    const float4* vp  = (const float4*)(g_v  + (size_t)col * 64 + h * 8);
    const float4* rkp = (const float4*)(relk + (size_t)bin * 64 + h * 8);
    const float4* rvp = (const float4*)(relv + (size_t)bin * 64 + h * 8);

    float4 q0 = qp[0],  q1 = qp[1];
    float4 k0 = kp[0],  k1 = kp[1];
    float4 rk0 = rkp[0], rk1 = rkp[1];

    float s =
        q0.x*(k0.x+rk0.x) + q0.y*(k0.y+rk0.y) + q0.z*(k0.z+rk0.z) + q0.w*(k0.w+rk0.w) +
        q1.x*(k1.x+rk1.x) + q1.y*(k1.y+rk1.y) + q1.z*(k1.z+rk1.z) + q1.w*(k1.w+rk1.w);
    float ex = __expf(s * SCALE);

    atomicAdd(&g_den[(size_t)row * NH + h], ex);

    float4 v0 = vp[0],  v1 = vp[1];
    float4 rv0 = rvp[0], rv1 = rvp[1];

    float* op = g_acc + (size_t)row * 64 + h * 8;
    asm volatile("red.global.add.v4.f32 [%0], {%1,%2,%3,%4};" ::
                 "l"(op),
                 "f"(ex*(v0.x+rv0.x)), "f"(ex*(v0.y+rv0.y)),
                 "f"(ex*(v0.z+rv0.z)), "f"(ex*(v0.w+rv0.w)) : "memory");
    asm volatile("red.global.add.v4.f32 [%0], {%1,%2,%3,%4};" ::
                 "l"(op + 4),
                 "f"(ex*(v1.x+rv1.x)), "f"(ex*(v1.y+rv1.y)),
                 "f"(ex*(v1.z+rv1.z)), "f"(ex*(v1.w+rv1.w)) : "memory");
}

// ---------------------------------------------------------------------------
// Output projection via tensor cores: out = (acc/den) @ Wo + bo
// smem: sB [8][8][32][4] ; sU union (raw W [64][64] -> X [128][68]) ;
//       sBias[64] ; sInv[128][8]
// ---------------------------------------------------------------------------
#define OUT_SB_F   (8 * 8 * 32 * 4)         // 8192 floats
#define OUT_SU_F   (128 * 68)               // 8704 floats (>= 64*64=4096)
#define OUT_SMEM_B ((OUT_SB_F + OUT_SU_F + 64 + 1024) * 4)

__global__ __launch_bounds__(256) void out_mma(
    const float* __restrict__ Wo, const float* __restrict__ bo,
    float* __restrict__ out)
{
    extern __shared__ float sm[];
    float* sB    = sm;
    float* sU    = sm + OUT_SB_F;
    float* sBias = sU + OUT_SU_F;
    float* sInv  = sBias + 64;
    const int tid = threadIdx.x;
    const int base = blockIdx.x * 128;

    // phase 1: raw W
    for (int i = tid; i < 4096; i += 256) sU[i] = Wo[i];
    if (tid < 64) sBias[tid] = bo[tid];
    __syncthreads();

    // phase 2: fragment-order W + inv-denominator staging
    for (int e = tid; e < 2048; e += 256) {
        int lane = e & 31, kstep = (e >> 5) & 7, nblk = e >> 8;
        int k0 = kstep * 8 + (lane & 3);
        int n  = nblk * 8 + (lane >> 2);
        float w0 = sU[k0 * 64 + n];
        float w1 = sU[(k0 + 4) * 64 + n];
        unsigned h0 = f2tf32(w0), h1 = f2tf32(w1);
        unsigned l0 = f2tf32(w0 - __uint_as_float(h0));
        unsigned l1 = f2tf32(w1 - __uint_as_float(h1));
        *(float4*)&sB[e * 4] = make_float4(__uint_as_float(h0), __uint_as_float(h1),
                                           __uint_as_float(l0), __uint_as_float(l1));
    }
    for (int i = tid; i < 1024; i += 256) {
        int r = i >> 3, h = i & 7;
        int node = base + r;
        float d = (node < NN) ? g_den[(size_t)node * NH + h] : 1.0f;
        sInv[i] = (d > 0.f) ? (1.0f / d) : 0.0f;
    }
    __syncthreads();

    // phase 3: X = acc * inv_den  into [128][68]
    for (int i = tid; i < 2048; i += 256) {
        int r = i >> 4, c4 = i & 15;
        int node = base + r;
        float4 t = make_float4(0.f, 0.f, 0.f, 0.f);
        if (node < NN) {
            t = ((const float4*)(g_acc + (size_t)node * 64))[c4];
            float inv = sInv[r * 8 + (c4 >> 1)];
            t.x *= inv; t.y *= inv; t.z *= inv; t.w *= inv;
        }
        *(float4*)&sU[r * 68 + c4 * 4] = t;
    }
    __syncthreads();

    // phase 4: mma
    const int w = tid >> 5, lane = tid & 31;
    const int grp = lane >> 2, tg = lane & 3;
    const float* xr0 = sU + (w * 16 + grp) * 68;
    const float* xr8 = sU + (w * 16 + grp + 8) * 68;

    unsigned ah[8][4], al[8][4];
    #pragma unroll
    for (int ks = 0; ks < 8; ks++) {
        float v0 = xr0[ks * 8 + tg],     v1 = xr8[ks * 8 + tg];
        float v2 = xr0[ks * 8 + tg + 4], v3 = xr8[ks * 8 + tg + 4];
        ah[ks][0] = f2tf32(v0); al[ks][0] = f2tf32(v0 - __uint_as_float(ah[ks][0]));
        ah[ks][1] = f2tf32(v1); al[ks][1] = f2tf32(v1 - __uint_as_float(ah[ks][1]));
        ah[ks][2] = f2tf32(v2); al[ks][2] = f2tf32(v2 - __uint_as_float(ah[ks][2]));
        ah[ks][3] = f2tf32(v3); al[ks][3] = f2tf32(v3 - __uint_as_float(ah[ks][3]));
    }

    const int row0 = base + w * 16 + grp;

    #pragma unroll 1
    for (int nb2 = 0; nb2 < 4; nb2++) {
        float cA0 = 0.f, cA1 = 0.f, cA2 = 0.f, cA3 = 0.f;
        float cB0 = 0.f, cB1 = 0.f, cB2 = 0.f, cB3 = 0.f;
        const float* pA = sB + ((nb2 * 2 + 0) * 256 + lane) * 4;
        const float* pB = sB + ((nb2 * 2 + 1) * 256 + lane) * 4;
        #pragma unroll
        for (int ks = 0; ks < 8; ks++) {
            float4 fA = *(const float4*)(pA + ks * 128);
            float4 fB = *(const float4*)(pB + ks * 128);
            unsigned bAh0 = __float_as_uint(fA.x), bAh1 = __float_as_uint(fA.y);
            unsigned bAl0 = __float_as_uint(fA.z), bAl1 = __float_as_uint(fA.w);
            unsigned bBh0 = __float_as_uint(fB.x), bBh1 = __float_as_uint(fB.y);
            unsigned bBl0 = __float_as_uint(fB.z), bBl1 = __float_as_uint(fB.w);
            MMA_TF32(cA0,cA1,cA2,cA3, ah[ks][0],ah[ks][1],ah[ks][2],ah[ks][3], bAh0,bAh1);
            MMA_TF32(cB0,cB1,cB2,cB3, ah[ks][0],ah[ks][1],ah[ks][2],ah[ks][3], bBh0,bBh1);
            MMA_TF32(cA0,cA1,cA2,cA3, al[ks][0],al[ks][1],al[ks][2],al[ks][3], bAh0,bAh1);
            MMA_TF32(cB0,cB1,cB2,cB3, al[ks][0],al[ks][1],al[ks][2],al[ks][3], bBh0,bBh1);
            MMA_TF32(cA0,cA1,cA2,cA3, ah[ks][0],ah[ks][1],ah[ks][2],ah[ks][3], bAl0,bAl1);
            MMA_TF32(cB0,cB1,cB2,cB3, ah[ks][0],ah[ks][1],ah[ks][2],ah[ks][3], bBl0,bBl1);
        }
        #pragma unroll
        for (int t = 0; t < 2; t++) {
            int nblk = nb2 * 2 + t;
            int ncol = nblk * 8 + tg * 2;
            float b0 = sBias[ncol], b1 = sBias[ncol + 1];
            float c0 = (t ? cB0 : cA0) + b0, c1 = (t ? cB1 : cA1) + b1;
            float c2 = (t ? cB2 : cA2) + b0, c3 = (t ? cB3 : cA3) + b1;
            if (row0 < NN)
                *(float2*)&out[(size_t)row0 * 64 + ncol] = make_float2(c0, c1);
            if (row0 + 8 < NN)
                *(float2*)&out[(size_t)(row0 + 8) * 64 + ncol] = make_float2(c2, c3);
        }
    }
}

// ---------------------------------------------------------------------------
extern "C" void kernel_launch(void* const* d_in, const int* in_sizes, int n_in,
                              void* d_out, int out_size)
{
    const float* x   = (const float*)d_in[0];
    const int*   ei  = (const int*)  d_in[1];
    const float* pos = (const float*)d_in[2];
    const float* Wq  = (const float*)d_in[3];
    const float* bq  = (const float*)d_in[4];
    const float* Wk  = (const float*)d_in[5];
    const float* bk  = (const float*)d_in[6];
    const float* Wv  = (const float*)d_in[7];
    const float* bv  = (const float*)d_in[8];
    const float* rk  = (const float*)d_in[9];
    const float* rv  = (const float*)d_in[10];
    const float* Wo  = (const float*)d_in[11];
    const float* bo  = (const float*)d_in[12];
    float* out = (float*)d_out;

    cudaFuncSetAttribute(qkv_mma, cudaFuncAttributeMaxDynamicSharedMemorySize, QKV_SMEM_B);
    cudaFuncSetAttribute(out_mma, cudaFuncAttributeMaxDynamicSharedMemorySize, OUT_SMEM_B);

    const int zero_threads = NN * (EMBED + NH) / 4;
    const int nblocks = (NN + 127) / 128;   // 391

    zero_kernel<<<(zero_threads + 255) / 256, 256>>>();
    qkv_mma   <<<nblocks, 256, QKV_SMEM_B>>>(x, Wq, bq, Wk, bk, Wv, bv);
    edge_kernel<<<(EE * 8) / 256, 256>>>(ei, pos, rk, rv);
    out_mma   <<<nblocks, 256, OUT_SMEM_B>>>(Wo, bo, out);
}